// round 11
// baseline (speedup 1.0000x reference)
#include <cuda_runtime.h>
#include <cuda_fp16.h>

#define NN 60000
#define EE 1200000
#define DD 64
#define OUTD 192   // K * D

// ---- device scratch ----
__device__ int    g_deg[NN];
__device__ int    g_rowptr[NN + 1];
__device__ int    g_cursor[NN];
__device__ int    g_col[EE];
__device__ float  g_dinv[NN];            // d^-1/2
__device__ __half g_Xs_h [NN * DD];      // fp16: X0 * d^-1/2   (gather src, pass 1)
__device__ __half g_X1s_h[NN * DD];      // fp16: X1 * d^-1/2   (gather src, pass 2)
__device__ float  g_X1  [NN * DD];       // fp32: raw X1 (for exact recurrence term)

// bit-reinterpret helpers (no-op in SASS)
__device__ __forceinline__ unsigned h2_bits(__half2 h) {
    return *(unsigned*)&h;
}
__device__ __forceinline__ float2 bits_f2(unsigned u) {
    __half2 h = *(__half2*)&u;
    return __half22float2(h);
}

__global__ void k_zero_deg() {
    int i = blockIdx.x * blockDim.x + threadIdx.x;
    if (i < NN) g_deg[i] = 0;
}

__global__ void k_deg(const int* __restrict__ dst) {
    int t = blockIdx.x * blockDim.x + threadIdx.x;
    if (t < EE / 4) {
        int4 d = ((const int4*)dst)[t];
        atomicAdd(&g_deg[d.x], 1);
        atomicAdd(&g_deg[d.y], 1);
        atomicAdd(&g_deg[d.z], 1);
        atomicAdd(&g_deg[d.w], 1);
    }
}

// Single-block chunked scan, int4-vectorized. chunk=60 (4-aligned, 1000*60=NN).
__global__ void k_scan() {
    const int T = 1024;
    const int CH = 60;
    int tid = threadIdx.x;
    int start = tid * CH;
    int sum = 0;
    if (start < NN) {
        const int4* p = (const int4*)(g_deg + start);
        #pragma unroll
        for (int i = 0; i < CH / 4; i++) {
            int4 v = p[i];
            sum += v.x + v.y + v.z + v.w;
        }
    }
    __shared__ int sh[T];
    sh[tid] = sum;
    __syncthreads();
    for (int off = 1; off < T; off <<= 1) {
        int v = (tid >= off) ? sh[tid - off] : 0;
        __syncthreads();
        sh[tid] += v;
        __syncthreads();
    }
    int run = sh[tid] - sum;   // exclusive prefix of this chunk
    if (start < NN) {
        const int4* p = (const int4*)(g_deg + start);
        int4* rp = (int4*)(g_rowptr + start);
        int4* cp = (int4*)(g_cursor + start);
        #pragma unroll
        for (int i = 0; i < CH / 4; i++) {
            int4 d = p[i];
            int4 r;
            r.x = run;
            r.y = r.x + d.x;
            r.z = r.y + d.y;
            r.w = r.z + d.z;
            run = r.w + d.w;
            rp[i] = r;
            cp[i] = r;
        }
    }
    if (tid == T - 1) g_rowptr[NN] = run;
}

// 16 threads per node, 1 float4 each: dinv, Xs_h = fp16(feat*dinv), out[:,0:64]=relu(feat)
__global__ void k_prep(const float* __restrict__ feat, float* __restrict__ out) {
    int t = blockIdx.x * blockDim.x + threadIdx.x;
    if (t >= NN * 16) return;
    int i = t >> 4;
    int c = (t & 15) << 2;
    float dinv = rsqrtf(fmaxf((float)g_deg[i], 1.0f));
    if ((t & 15) == 0) g_dinv[i] = dinv;
    float4 f = *(const float4*)(feat + (size_t)i * DD + c);
    __half2 h0 = __float22half2_rn(make_float2(f.x * dinv, f.y * dinv));
    __half2 h1 = __float22half2_rn(make_float2(f.z * dinv, f.w * dinv));
    uint2 packed = make_uint2(h2_bits(h0), h2_bits(h1));
    *(uint2*)((char*)g_Xs_h + (size_t)i * DD * 2 + c * 2) = packed;
    *(float4*)(out + (size_t)i * OUTD + c) =
        make_float4(fmaxf(f.x, 0.f), fmaxf(f.y, 0.f), fmaxf(f.z, 0.f), fmaxf(f.w, 0.f));
}

__global__ void k_fill(const int* __restrict__ src, const int* __restrict__ dst) {
    int t = blockIdx.x * blockDim.x + threadIdx.x;
    if (t < EE / 4) {
        int4 s = ((const int4*)src)[t];
        int4 d = ((const int4*)dst)[t];
        int p0 = atomicAdd(&g_cursor[d.x], 1); g_col[p0] = s.x;
        int p1 = atomicAdd(&g_cursor[d.y], 1); g_col[p1] = s.y;
        int p2 = atomicAdd(&g_cursor[d.z], 1); g_col[p2] = s.z;
        int p3 = atomicAdd(&g_cursor[d.w], 1); g_col[p3] = s.w;
    }
}

__device__ __forceinline__ void accum8(float* acc, uint4 p) {
    float2 f0 = bits_f2(p.x), f1 = bits_f2(p.y);
    float2 f2 = bits_f2(p.z), f3 = bits_f2(p.w);
    acc[0] += f0.x; acc[1] += f0.y; acc[2] += f1.x; acc[3] += f1.y;
    acc[4] += f2.x; acc[5] += f2.y; acc[6] += f3.x; acc[7] += f3.y;
}

// Warp gathers fp16 rows (128B each) for one node.
// Indices staged in registers (coalesced lane-per-edge load) + shfl broadcast.
// 4 groups of 8 lanes; each group loads one full row per LDG.128 (16B/lane).
// Inner loop keeps 4 LDG.128 in flight (16 edges). After reduction,
// lanes 0-7 hold fp32 sums for features [8*fl, 8*fl+8).
__device__ __forceinline__ void gather8(const __half* __restrict__ table,
                                        int beg, int end, int lane, float* acc) {
    int group = lane >> 3;   // 0..3 : which edge within a 4-edge pack
    int fl = lane & 7;       // 16-byte feature slice within the row
    int ne = end - beg;
    const char* base = (const char*)table;
    for (int b0 = 0; b0 < ne; b0 += 32) {
        int my = beg + b0 + lane;
        int idx_l = (my < end) ? g_col[my] : 0;
        int lim = min(32, ne - b0);
        for (int c = 0; c < lim; c += 16) {
            int e0 = c + group, e1 = c + 4 + group, e2 = c + 8 + group, e3 = c + 12 + group;
            int s0 = __shfl_sync(0xFFFFFFFF, idx_l, e0);
            int s1 = __shfl_sync(0xFFFFFFFF, idx_l, e1);
            int s2 = __shfl_sync(0xFFFFFFFF, idx_l, e2);
            int s3 = __shfl_sync(0xFFFFFFFF, idx_l, e3);
            bool v0 = e0 < lim, v1 = e1 < lim, v2 = e2 < lim, v3 = e3 < lim;
            uint4 p0, p1, p2, p3;
            if (v0) p0 = *(const uint4*)(base + (size_t)s0 * 128 + fl * 16);
            if (v1) p1 = *(const uint4*)(base + (size_t)s1 * 128 + fl * 16);
            if (v2) p2 = *(const uint4*)(base + (size_t)s2 * 128 + fl * 16);
            if (v3) p3 = *(const uint4*)(base + (size_t)s3 * 128 + fl * 16);
            if (v0) accum8(acc, p0);
            if (v1) accum8(acc, p1);
            if (v2) accum8(acc, p2);
            if (v3) accum8(acc, p3);
        }
    }
    #pragma unroll
    for (int j = 0; j < 8; j++) {
        acc[j] += __shfl_xor_sync(0xFFFFFFFF, acc[j], 8);
        acc[j] += __shfl_xor_sync(0xFFFFFFFF, acc[j], 16);
    }
}

// pass 1: h = dinv * sum(Xs[col]); X1 = -rn*h + (rn-1)*X0
// writes g_X1 (fp32), g_X1s_h (fp16 scaled), out[:, 64:128] = relu(X1)
__global__ void k_spmm1(const float* __restrict__ feat,
                        const float* __restrict__ lambda_max,
                        float* __restrict__ out) {
    int w = (blockIdx.x * blockDim.x + threadIdx.x) >> 5;
    int lane = threadIdx.x & 31;
    if (w >= NN) return;
    int beg = g_rowptr[w];
    int end = g_rowptr[w + 1];
    float acc[8] = {0.f, 0.f, 0.f, 0.f, 0.f, 0.f, 0.f, 0.f};
    gather8(g_Xs_h, beg, end, lane, acc);
    if (lane < 8) {
        float dinv = g_dinv[w];
        float rn = 2.0f / lambda_max[0];
        float a = -rn * dinv;
        float b = rn - 1.0f;
        const float4* fp = (const float4*)(feat + (size_t)w * DD + lane * 8);
        float4 xa = fp[0], xb = fp[1];
        float x1[8];
        x1[0] = a * acc[0] + b * xa.x;
        x1[1] = a * acc[1] + b * xa.y;
        x1[2] = a * acc[2] + b * xa.z;
        x1[3] = a * acc[3] + b * xa.w;
        x1[4] = a * acc[4] + b * xb.x;
        x1[5] = a * acc[5] + b * xb.y;
        x1[6] = a * acc[6] + b * xb.z;
        x1[7] = a * acc[7] + b * xb.w;
        float4* xp = (float4*)(g_X1 + (size_t)w * DD + lane * 8);
        xp[0] = make_float4(x1[0], x1[1], x1[2], x1[3]);
        xp[1] = make_float4(x1[4], x1[5], x1[6], x1[7]);
        __half2 h0 = __float22half2_rn(make_float2(x1[0] * dinv, x1[1] * dinv));
        __half2 h1 = __float22half2_rn(make_float2(x1[2] * dinv, x1[3] * dinv));
        __half2 h2 = __float22half2_rn(make_float2(x1[4] * dinv, x1[5] * dinv));
        __half2 h3 = __float22half2_rn(make_float2(x1[6] * dinv, x1[7] * dinv));
        *(uint4*)((char*)g_X1s_h + (size_t)w * 128 + lane * 16) =
            make_uint4(h2_bits(h0), h2_bits(h1), h2_bits(h2), h2_bits(h3));
        float4* op = (float4*)(out + (size_t)w * OUTD + DD + lane * 8);
        op[0] = make_float4(fmaxf(x1[0], 0.f), fmaxf(x1[1], 0.f),
                            fmaxf(x1[2], 0.f), fmaxf(x1[3], 0.f));
        op[1] = make_float4(fmaxf(x1[4], 0.f), fmaxf(x1[5], 0.f),
                            fmaxf(x1[6], 0.f), fmaxf(x1[7], 0.f));
    }
}

// pass 2: h2 = dinv * sum(X1s[col]); X2 = -2*rn*h2 + 2*(rn-1)*X1 - X0
// writes out[:, 128:192] = relu(X2). X1 term uses the exact fp32 buffer.
__global__ void k_spmm2(const float* __restrict__ feat,
                        const float* __restrict__ lambda_max,
                        float* __restrict__ out) {
    int w = (blockIdx.x * blockDim.x + threadIdx.x) >> 5;
    int lane = threadIdx.x & 31;
    if (w >= NN) return;
    int beg = g_rowptr[w];
    int end = g_rowptr[w + 1];
    float acc[8] = {0.f, 0.f, 0.f, 0.f, 0.f, 0.f, 0.f, 0.f};
    gather8(g_X1s_h, beg, end, lane, acc);
    if (lane < 8) {
        float dinv = g_dinv[w];
        float rn = 2.0f / lambda_max[0];
        float a = -2.0f * rn * dinv;
        float b = 2.0f * (rn - 1.0f);
        const float4* fp = (const float4*)(feat + (size_t)w * DD + lane * 8);
        const float4* x1p = (const float4*)(g_X1 + (size_t)w * DD + lane * 8);
        float4 xa = fp[0], xb = fp[1];
        float4 ya = x1p[0], yb = x1p[1];
        float x2[8];
        x2[0] = a * acc[0] + b * ya.x - xa.x;
        x2[1] = a * acc[1] + b * ya.y - xa.y;
        x2[2] = a * acc[2] + b * ya.z - xa.z;
        x2[3] = a * acc[3] + b * ya.w - xa.w;
        x2[4] = a * acc[4] + b * yb.x - xb.x;
        x2[5] = a * acc[5] + b * yb.y - xb.y;
        x2[6] = a * acc[6] + b * yb.z - xb.z;
        x2[7] = a * acc[7] + b * yb.w - xb.w;
        float4* op = (float4*)(out + (size_t)w * OUTD + 2 * DD + lane * 8);
        op[0] = make_float4(fmaxf(x2[0], 0.f), fmaxf(x2[1], 0.f),
                            fmaxf(x2[2], 0.f), fmaxf(x2[3], 0.f));
        op[1] = make_float4(fmaxf(x2[4], 0.f), fmaxf(x2[5], 0.f),
                            fmaxf(x2[6], 0.f), fmaxf(x2[7], 0.f));
    }
}

extern "C" void kernel_launch(void* const* d_in, const int* in_sizes, int n_in,
                              void* d_out, int out_size) {
    const float* feat       = (const float*)d_in[0];
    const int*   src        = (const int*)d_in[1];
    const int*   dst        = (const int*)d_in[2];
    const float* lambda_max = (const float*)d_in[3];
    float* out = (float*)d_out;

    const int TB = 256;
    k_zero_deg<<<(NN + TB - 1) / TB, TB>>>();
    k_deg<<<(EE / 4 + TB - 1) / TB, TB>>>(dst);
    k_scan<<<1, 1024>>>();
    k_prep<<<(NN * 16 + TB - 1) / TB, TB>>>(feat, out);
    k_fill<<<(EE / 4 + TB - 1) / TB, TB>>>(src, dst);
    k_spmm1<<<(NN * 32 + TB - 1) / TB, TB>>>(feat, lambda_max, out);
    k_spmm2<<<(NN * 32 + TB - 1) / TB, TB>>>(feat, lambda_max, out);
}